// round 2
// baseline (speedup 1.0000x reference)
#include <cuda_runtime.h>

#define NN 52      // nodes
#define NE 832     // edges
#define E2 884     // edges + self loops
#define FD 256     // feature dim
#define NT 256     // threads per CTA

union F2U { float2 f; unsigned long long u; };

__device__ __forceinline__ unsigned long long pack2(float a, float b){
    F2U t; t.f = make_float2(a, b); return t.u;
}
__device__ __forceinline__ float2 unpack2(unsigned long long v){
    F2U t; t.u = v; return t.f;
}
// packed dual-fp32 FMA (sm_100+): d.lo += a.lo*b.lo ; d.hi += a.hi*b.hi
__device__ __forceinline__ void fma2(unsigned long long& d,
                                     unsigned long long a,
                                     unsigned long long b){
    asm("fma.rn.f32x2 %0, %1, %2, %0;" : "+l"(d) : "l"(a), "l"(b));
}
__device__ __forceinline__ float sigmoidf_(float x){
    return 1.f / (1.f + __expf(-x));
}

// shared memory accounting
constexpr int SM_FLOATS = NN*FD*2 + E2 + NN*5 + FD*5;
constexpr int SM_INTS   = E2*3 + (NN+1) + NN;
constexpr int SMEM_BYTES = (SM_FLOATS + SM_INTS) * 4;

__global__ void __launch_bounds__(NT, 1)
gcab_kernel(const float* __restrict__ xg, const void* __restrict__ eig,
            const float* __restrict__ W0, const float* __restrict__ as0,
            const float* __restrict__ ad0, const float* __restrict__ b0,
            const float* __restrict__ W1, const float* __restrict__ as1,
            const float* __restrict__ ad1, const float* __restrict__ b1,
            const float* __restrict__ Wm, const float* __restrict__ bm,
            const float* __restrict__ wgp, const float* __restrict__ bgp,
            float* __restrict__ outg)
{
    extern __shared__ float sm[];
    float* sA    = sm;                 // [52][256] : x -> h0 -> h
    float* sB    = sA + NN*FD;         // [52][256] : xp (per round)
    float* sAl   = sB + NN*FD;         // [884]     : edge logits -> alpha
    float* sAsrc = sAl + E2;           // [52]
    float* sAdst = sAsrc + NN;         // [52]
    float* sHmax = sAdst + NN;         // [52]
    float* sDinv = sHmax + NN;         // [52]
    float* sMno  = sDinv + NN;         // [52]
    float* sAs   = sMno + NN;          // [256]
    float* sAd   = sAs + FD;           // [256]
    float* sAvg  = sAd + FD;           // [256]
    float* sMx   = sAvg + FD;          // [256]
    float* sMch  = sMx + FD;           // [256]
    int*   sS    = (int*)(sMch + FD);  // [884] src
    int*   sD    = sS + E2;            // [884] dst
    int*   sIdx  = sD + E2;            // [884] CSR edge ids
    int*   sOff  = sIdx + E2;          // [53]
    int*   sCnt  = sOff + (NN+1);      // [52]
    __shared__ int sIs64;

    const int tid  = threadIdx.x;
    const int g    = blockIdx.x;
    const int lane = tid & 31, wrp = tid >> 5;

    // ------- detect edge_index dtype (int64 vs int32) -------
    // int64 little-endian values in [0,52): every high word is 0.
    if (tid == 0){
        const int* e32 = (const int*)eig;
        int flag = 1;
        #pragma unroll 1
        for (int i = 0; i < 32; i++){
            if (e32[2*i + 1] != 0){ flag = 0; break; }
        }
        sIs64 = flag;
    }

    // ---------------- load x, zero counts ----------------
    {
        const float4* xs = reinterpret_cast<const float4*>(xg + (size_t)g*NN*FD);
        float4* d4 = reinterpret_cast<float4*>(sA);
        for (int i = tid; i < NN*FD/4; i += NT) d4[i] = xs[i];
        if (tid < NN) sCnt[tid] = 0;
    }
    __syncthreads();

    // ---------------- load edges (dtype-dispatched) ----------------
    {
        const int is64 = sIs64;
        const long long* ei64 = (const long long*)eig + (size_t)g*2*NE;
        const int*       ei32 = (const int*)eig       + (size_t)g*2*NE;
        for (int e = tid; e < E2; e += NT){
            int s, d;
            if (e < NE){
                if (is64){ s = (int)ei64[e]; d = (int)ei64[NE + e]; }
                else     { s = ei32[e];      d = ei32[NE + e]; }
            } else {
                s = e - NE; d = e - NE;
            }
            sS[e] = s; sD[e] = d;
        }
    }
    __syncthreads();
    // indegree counts (int atomics, deterministic)
    for (int e = tid; e < E2; e += NT) atomicAdd(&sCnt[sD[e]], 1);
    __syncthreads();
    if (tid == 0){
        int acc = 0;
        for (int i = 0; i < NN; i++){ sOff[i] = acc; acc += sCnt[i]; }
        sOff[NN] = acc;
    }
    __syncthreads();
    // deterministic CSR fill: thread dd scans edges in order
    if (tid < NN){
        int pos = sOff[tid];
        for (int e = 0; e < E2; e++) if (sD[e] == tid) sIdx[pos++] = e;
        sDinv[tid] = rsqrtf((float)sCnt[tid]);   // GCN symmetric norm (deg >= 1)
    }
    __syncthreads();

    // ---------------- two GAT rounds ----------------
    for (int rnd = 0; rnd < 2; rnd++){
        const float* W  = rnd ? W1  : W0;
        const float* av = rnd ? as1 : as0;
        const float* dv = rnd ? ad1 : ad0;
        const float* bb = rnd ? b1  : b0;
        for (int i = tid; i < FD; i += NT){ sAs[i] = av[i]; sAd[i] = dv[i]; }

        // GEMM: sB[52][256] = sA[52][256] @ W[256][256], thread = out column
        {
            unsigned long long acc[NN];
#pragma unroll
            for (int i = 0; i < NN; i++) acc[i] = 0ull;
            const float2* sA2 = reinterpret_cast<const float2*>(sA);
            const float*  wc  = W + tid;
#pragma unroll 2
            for (int kp = 0; kp < FD/2; kp++){
                float w0 = wc[(2*kp  )*FD];
                float w1 = wc[(2*kp+1)*FD];
                unsigned long long wv = pack2(w0, w1);
#pragma unroll
                for (int i = 0; i < NN; i++){
                    F2U xv; xv.f = sA2[i*(FD/2) + kp];
                    fma2(acc[i], xv.u, wv);
                }
            }
#pragma unroll
            for (int i = 0; i < NN; i++){
                float2 a = unpack2(acc[i]);
                sB[i*FD + tid] = a.x + a.y;
            }
        }
        __syncthreads();

        // asrc/adst per row: warp-per-row reductions
        for (int r = wrp; r < NN; r += 8){
            float sa = 0.f, sd = 0.f;
#pragma unroll
            for (int t = 0; t < 8; t++){
                float v = sB[r*FD + lane + 32*t];
                sa += v * sAs[lane + 32*t];
                sd += v * sAd[lane + 32*t];
            }
#pragma unroll
            for (int o = 16; o; o >>= 1){
                sa += __shfl_down_sync(0xffffffffu, sa, o);
                sd += __shfl_down_sync(0xffffffffu, sd, o);
            }
            if (lane == 0){ sAsrc[r] = sa; sAdst[r] = sd; }
        }
        __syncthreads();

        // edge logits (leaky relu 0.2)
        for (int e = tid; e < E2; e += NT){
            float el = sAsrc[sS[e]] + sAdst[sD[e]];
            sAl[e] = el > 0.f ? el : 0.2f * el;
        }
        __syncthreads();

        // per-dest softmax over incoming edges (deterministic order)
        if (tid < NN){
            int beg = sOff[tid], end = sOff[tid+1];
            float m = -3.0e38f;
            for (int t = beg; t < end; t++) m = fmaxf(m, sAl[sIdx[t]]);
            float ssum = 0.f;
            for (int t = beg; t < end; t++){
                float w = __expf(sAl[sIdx[t]] - m);
                sAl[sIdx[t]] = w;
                ssum += w;
            }
            float inv = 1.f / ssum;
            for (int t = beg; t < end; t++) sAl[sIdx[t]] *= inv;
        }
        __syncthreads();

        // aggregation: 128 column-pairs x 2 row halves, packed FMA
        {
            const int p  = tid & 127;
            const int r0 = (tid >> 7) * 26;
            const float2* sB2  = reinterpret_cast<const float2*>(sB);
            float2*       sA2w = reinterpret_cast<float2*>(sA);
            float2 bbv = reinterpret_cast<const float2*>(bb)[p];
            for (int dd = r0; dd < r0 + 26; dd++){
                int beg = sOff[dd], end = sOff[dd+1];
                unsigned long long acc = 0ull;
                for (int t = beg; t < end; t++){
                    int e  = sIdx[t];
                    float al = sAl[e];
                    F2U xv; xv.f = sB2[sS[e]*(FD/2) + p];
                    fma2(acc, xv.u, pack2(al, al));
                }
                float2 r = unpack2(acc);
                if (rnd == 0){
                    sA2w[dd*(FD/2)+p] = make_float2(r.x + bbv.x, r.y + bbv.y);
                } else {
                    float2 old = sA2w[dd*(FD/2)+p];
                    sA2w[dd*(FD/2)+p] =
                        make_float2(fmaxf(r.x + bbv.x + old.x, 0.f),
                                    fmaxf(r.y + bbv.y + old.y, 0.f));
                }
            }
        }
        __syncthreads();
    }

    // ---------------- channel attention ----------------
    {
        float avv = 0.f, mx = -3.0e38f;
        for (int dd = 0; dd < NN; dd++){
            float v = sA[dd*FD + tid];
            avv += v; mx = fmaxf(mx, v);
        }
        sAvg[tid] = avv * (1.f/52.f);
        sMx[tid]  = mx;
    }
    __syncthreads();
    {
        float aA = 0.f, aM = 0.f;
        const float* wc = Wm + tid;
#pragma unroll 4
        for (int k = 0; k < FD; k++){
            float w = wc[k*FD];
            aA += sAvg[k]*w;
            aM += sMx[k]*w;
        }
        float bj = bm[tid];
        float m = sigmoidf_(fmaxf(aA + bj, 0.f) + fmaxf(aM + bj, 0.f));
        sMch[tid] = m;
        for (int dd = 0; dd < NN; dd++) sA[dd*FD + tid] *= m;  // h *= mch
    }
    __syncthreads();

    // ---------------- node attention ----------------
    // row max over features (warp per row)
    for (int r = wrp; r < NN; r += 8){
        float mx = -3.0e38f;
#pragma unroll
        for (int t = 0; t < 8; t++) mx = fmaxf(mx, sA[r*FD + lane + 32*t]);
#pragma unroll
        for (int o = 16; o; o >>= 1)
            mx = fmaxf(mx, __shfl_down_sync(0xffffffffu, mx, o));
        if (lane == 0) sHmax[r] = mx;
    }
    __syncthreads();
    // 1->1 GCN with symmetric norm + sigmoid
    if (tid < NN){
        float s = 0.f;
        int beg = sOff[tid], end = sOff[tid+1];
        for (int t = beg; t < end; t++){
            int ss = sS[sIdx[t]];
            s += sDinv[ss] * sHmax[ss];
        }
        float aggv = sDinv[tid] * s * wgp[0] + bgp[0];
        sMno[tid] = sigmoidf_(aggv);
    }
    __syncthreads();

    // ---------------- final write ----------------
    {
        float* op = outg + (size_t)g*NN*FD;
        for (int dd = 0; dd < NN; dd++)
            op[dd*FD + tid] = sA[dd*FD + tid] * sMno[dd];
    }
}

extern "C" void kernel_launch(void* const* d_in, const int* in_sizes, int n_in,
                              void* d_out, int out_size)
{
    const float* x   = (const float*)d_in[0];
    const void*  ei  = d_in[1];
    const float* W0  = (const float*)d_in[2];
    const float* as0 = (const float*)d_in[3];
    const float* ad0 = (const float*)d_in[4];
    const float* b0  = (const float*)d_in[5];
    const float* W1  = (const float*)d_in[6];
    const float* as1 = (const float*)d_in[7];
    const float* ad1 = (const float*)d_in[8];
    const float* b1  = (const float*)d_in[9];
    const float* Wm  = (const float*)d_in[10];
    const float* bm  = (const float*)d_in[11];
    const float* wg  = (const float*)d_in[12];
    const float* bg  = (const float*)d_in[13];
    float* out = (float*)d_out;

    int B = in_sizes[0] / (NN*FD);

    cudaFuncSetAttribute(gcab_kernel,
                         cudaFuncAttributeMaxDynamicSharedMemorySize,
                         SMEM_BYTES);
    gcab_kernel<<<B, NT, SMEM_BYTES>>>(x, ei, W0, as0, ad0, b0,
                                       W1, as1, ad1, b1, Wm, bm, wg, bg, out);
}

// round 3
// speedup vs baseline: 1.5299x; 1.5299x over previous
#include <cuda_runtime.h>

#define NN 52      // nodes
#define NE 832     // edges
#define E2 884     // edges + self loops
#define FD 256     // feature dim
#define NT 512     // threads per CTA
#define RS 54      // padded row stride of transposed tile (even, low-conflict)

union F2U { float2 f; unsigned long long u; };

__device__ __forceinline__ unsigned long long pack2(float a, float b){
    F2U t; t.f = make_float2(a, b); return t.u;
}
__device__ __forceinline__ float2 unpack2(unsigned long long v){
    F2U t; t.u = v; return t.f;
}
// packed dual-fp32 FMA (sm_100+): d.lo += a.lo*b.lo ; d.hi += a.hi*b.hi
__device__ __forceinline__ void fma2(unsigned long long& d,
                                     unsigned long long a,
                                     unsigned long long b){
    asm("fma.rn.f32x2 %0, %1, %2, %0;" : "+l"(d) : "l"(a), "l"(b));
}
__device__ __forceinline__ float sigmoidf_(float x){
    return 1.f / (1.f + __expf(-x));
}

// shared memory accounting (floats + ints)
constexpr int SM_FLOATS = FD*RS + NN*FD + E2 + NN*5 + FD*5 + NT*2;
constexpr int SM_INTS   = E2*3 + (NN+1) + NN;
constexpr int SMEM_BYTES = (SM_FLOATS + SM_INTS) * 4;

__global__ void __launch_bounds__(NT, 1)
gcab_kernel(const float* __restrict__ xg, const void* __restrict__ eig,
            const float* __restrict__ W0, const float* __restrict__ as0,
            const float* __restrict__ ad0, const float* __restrict__ b0,
            const float* __restrict__ W1, const float* __restrict__ as1,
            const float* __restrict__ ad1, const float* __restrict__ b1,
            const float* __restrict__ Wm, const float* __restrict__ bm,
            const float* __restrict__ wgp, const float* __restrict__ bgp,
            float* __restrict__ outg)
{
    extern __shared__ float sm[];
    float* sAT   = sm;                 // [256][54] transposed activations (x -> h0 -> h)
    float* sB    = sAT + FD*RS;        // [52][256] xp (row-major)
    float* sAl   = sB + NN*FD;         // [884] edge logits -> alpha
    float* sAsrc = sAl + E2;           // [52]
    float* sAdst = sAsrc + NN;         // [52]
    float* sHmax = sAdst + NN;         // [52]
    float* sDinv = sHmax + NN;         // [52]
    float* sMno  = sDinv + NN;         // [52]
    float* sAs   = sMno + NN;          // [256]
    float* sAd   = sAs + FD;           // [256]
    float* sAvg  = sAd + FD;           // [256]
    float* sMx   = sAvg + FD;          // [256]
    float* sMch  = sMx + FD;           // [256]
    float* sPa   = sMch + FD;          // [512] scratch partial
    float* sPm   = sPa + NT;           // [512] scratch partial
    int*   sS    = (int*)(sPm + NT);   // [884] src
    int*   sD    = sS + E2;            // [884] dst
    int*   sIdx  = sD + E2;            // [884] CSR edge ids
    int*   sOff  = sIdx + E2;          // [53]
    int*   sCnt  = sOff + (NN+1);      // [52]
    __shared__ int sIs64;

    const int tid  = threadIdx.x;
    const int g    = blockIdx.x;
    const int lane = tid & 31, wrp = tid >> 5;

    // ------- detect edge_index dtype (int64 vs int32) -------
    if (tid == 0){
        const int* e32 = (const int*)eig;
        int flag = 1;
        #pragma unroll 1
        for (int i = 0; i < 32; i++){
            if (e32[2*i + 1] != 0){ flag = 0; break; }
        }
        sIs64 = flag;
    }

    // ---------------- load x (transposed) ----------------
    {
        const float4* xs = reinterpret_cast<const float4*>(xg + (size_t)g*NN*FD);
        for (int i = tid; i < NN*FD/4; i += NT){
            int row = i >> 6;         // 64 float4 per row
            int c4  = i & 63;
            float4 v = xs[i];
            sAT[(4*c4+0)*RS + row] = v.x;
            sAT[(4*c4+1)*RS + row] = v.y;
            sAT[(4*c4+2)*RS + row] = v.z;
            sAT[(4*c4+3)*RS + row] = v.w;
        }
        if (tid < NN) sCnt[tid] = 0;
    }
    __syncthreads();

    // ---------------- load edges ----------------
    {
        const int is64 = sIs64;
        const long long* ei64 = (const long long*)eig + (size_t)g*2*NE;
        const int*       ei32 = (const int*)eig       + (size_t)g*2*NE;
        for (int e = tid; e < E2; e += NT){
            int s, d;
            if (e < NE){
                if (is64){ s = (int)ei64[e]; d = (int)ei64[NE + e]; }
                else     { s = ei32[e];      d = ei32[NE + e]; }
            } else {
                s = e - NE; d = e - NE;
            }
            sS[e] = s; sD[e] = d;
        }
    }
    __syncthreads();
    for (int e = tid; e < E2; e += NT) atomicAdd(&sCnt[sD[e]], 1);
    __syncthreads();
    if (tid == 0){
        int acc = 0;
        for (int i = 0; i < NN; i++){ sOff[i] = acc; acc += sCnt[i]; }
        sOff[NN] = acc;
    }
    __syncthreads();
    // deterministic CSR fill via warp ballot (edge order preserved)
    for (int nd = wrp; nd < NN; nd += 16){
        int pos = sOff[nd];
        for (int base = 0; base < E2; base += 32){
            int e = base + lane;
            bool m = (e < E2) && (sD[e] == nd);
            unsigned mask = __ballot_sync(0xffffffffu, m);
            if (m){
                int r = __popc(mask & ((1u << lane) - 1u));
                sIdx[pos + r] = e;
            }
            pos += __popc(mask);
        }
    }
    if (tid < NN) sDinv[tid] = rsqrtf((float)sCnt[tid]);
    __syncthreads();

    // GEMM thread mapping
    const int cg = tid & 127;        // column pair: cols 2cg, 2cg+1
    const int rg = (tid >> 7) & 1;   // row group: rows rg*26 .. rg*26+25 (13 pairs)
    const int kh = tid >> 8;         // k half

    // ---------------- two GAT rounds ----------------
    for (int rnd = 0; rnd < 2; rnd++){
        const float* W  = rnd ? W1  : W0;
        const float* av = rnd ? as1 : as0;
        const float* dv = rnd ? ad1 : ad0;
        const float* bb = rnd ? b1  : b0;
        for (int i = tid; i < FD; i += NT){ sAs[i] = av[i]; sAd[i] = dv[i]; }

        // GEMM: sB[52][256] = A[52][256] @ W[256][256]
        // thread tile: 13 row-pairs x 2 cols, half of k
        {
            unsigned long long acc[13][2];
#pragma unroll
            for (int i = 0; i < 13; i++){ acc[i][0] = 0ull; acc[i][1] = 0ull; }
            const float* wp = W + (size_t)(kh*128)*FD + 2*cg;
            const float* xb = sAT + (kh*128)*RS + rg*26;
#pragma unroll 2
            for (int kk = 0; kk < 128; kk++){
                float2 w = *reinterpret_cast<const float2*>(wp); wp += FD;
                unsigned long long w0 = pack2(w.x, w.x);
                unsigned long long w1 = pack2(w.y, w.y);
                const float2* xr = reinterpret_cast<const float2*>(xb); xb += RS;
#pragma unroll
                for (int i = 0; i < 13; i++){
                    F2U xv; xv.f = xr[i];
                    fma2(acc[i][0], xv.u, w0);
                    fma2(acc[i][1], xv.u, w1);
                }
            }
            // k-half 0 writes, k-half 1 accumulates
            if (kh == 0){
#pragma unroll
                for (int i = 0; i < 13; i++){
                    float2 c0 = unpack2(acc[i][0]);
                    float2 c1 = unpack2(acc[i][1]);
                    int r0 = rg*26 + 2*i;
                    reinterpret_cast<float2*>(sB + r0*FD)[cg]     = make_float2(c0.x, c1.x);
                    reinterpret_cast<float2*>(sB + (r0+1)*FD)[cg] = make_float2(c0.y, c1.y);
                }
            }
            __syncthreads();
            if (kh == 1){
#pragma unroll
                for (int i = 0; i < 13; i++){
                    float2 c0 = unpack2(acc[i][0]);
                    float2 c1 = unpack2(acc[i][1]);
                    int r0 = rg*26 + 2*i;
                    float2* p0 = &reinterpret_cast<float2*>(sB + r0*FD)[cg];
                    float2* p1 = &reinterpret_cast<float2*>(sB + (r0+1)*FD)[cg];
                    float2 o0 = *p0, o1 = *p1;
                    *p0 = make_float2(o0.x + c0.x, o0.y + c1.x);
                    *p1 = make_float2(o1.x + c0.y, o1.y + c1.y);
                }
            }
            __syncthreads();
        }

        // asrc/adst per row: warp-per-row reductions (16 warps)
        for (int r = wrp; r < NN; r += 16){
            float sa = 0.f, sd = 0.f;
#pragma unroll
            for (int t = 0; t < 8; t++){
                float v = sB[r*FD + lane + 32*t];
                sa += v * sAs[lane + 32*t];
                sd += v * sAd[lane + 32*t];
            }
#pragma unroll
            for (int o = 16; o; o >>= 1){
                sa += __shfl_down_sync(0xffffffffu, sa, o);
                sd += __shfl_down_sync(0xffffffffu, sd, o);
            }
            if (lane == 0){ sAsrc[r] = sa; sAdst[r] = sd; }
        }
        __syncthreads();

        // edge logits (leaky relu 0.2)
        for (int e = tid; e < E2; e += NT){
            float el = sAsrc[sS[e]] + sAdst[sD[e]];
            sAl[e] = el > 0.f ? el : 0.2f * el;
        }
        __syncthreads();

        // per-dest softmax over incoming edges
        if (tid < NN){
            int beg = sOff[tid], end = sOff[tid+1];
            float m = -3.0e38f;
            for (int t = beg; t < end; t++) m = fmaxf(m, sAl[sIdx[t]]);
            float ssum = 0.f;
            for (int t = beg; t < end; t++){
                float w = __expf(sAl[sIdx[t]] - m);
                sAl[sIdx[t]] = w;
                ssum += w;
            }
            float inv = 1.f / ssum;
            for (int t = beg; t < end; t++) sAl[sIdx[t]] *= inv;
        }
        __syncthreads();

        // aggregation: 128 column-pairs x 4 row quarters; writes transposed sAT
        {
            const int p  = tid & 127;
            const int q  = tid >> 7;          // 0..3
            const float2* sB2 = reinterpret_cast<const float2*>(sB);
            float2 bbv = reinterpret_cast<const float2*>(bb)[p];
            for (int dd = q*13; dd < q*13 + 13; dd++){
                int beg = sOff[dd], end = sOff[dd+1];
                unsigned long long acc = 0ull;
                for (int t = beg; t < end; t++){
                    int e  = sIdx[t];
                    float al = sAl[e];
                    F2U xv; xv.f = sB2[sS[e]*(FD/2) + p];
                    fma2(acc, xv.u, pack2(al, al));
                }
                float2 r = unpack2(acc);
                float v0 = r.x + bbv.x;
                float v1 = r.y + bbv.y;
                float* a0 = &sAT[(2*p  )*RS + dd];
                float* a1 = &sAT[(2*p+1)*RS + dd];
                if (rnd == 1){
                    v0 = fmaxf(v0 + *a0, 0.f);
                    v1 = fmaxf(v1 + *a1, 0.f);
                }
                *a0 = v0;
                *a1 = v1;
            }
        }
        __syncthreads();
    }

    // ---------------- channel attention ----------------
    {
        const int j = tid & 255, half = tid >> 8;
        float s = 0.f, m = -3.0e38f;
        for (int r = half*26; r < half*26 + 26; r++){
            float v = sAT[j*RS + r];
            s += v; m = fmaxf(m, v);
        }
        sPa[tid] = s; sPm[tid] = m;
    }
    __syncthreads();
    if (tid < FD){
        sAvg[tid] = (sPa[tid] + sPa[tid + 256]) * (1.f/52.f);
        sMx[tid]  = fmaxf(sPm[tid], sPm[tid + 256]);
    }
    __syncthreads();
    {
        const int j = tid & 255, half = tid >> 8;
        float aA = 0.f, aM = 0.f;
        const float* wc = Wm + j;
#pragma unroll 4
        for (int k = half*128; k < half*128 + 128; k++){
            float w = wc[k*FD];
            aA += sAvg[k]*w;
            aM += sMx[k]*w;
        }
        sPa[tid] = aA; sPm[tid] = aM;
    }
    __syncthreads();
    if (tid < FD){
        float aA = sPa[tid] + sPa[tid + 256];
        float aM = sPm[tid] + sPm[tid + 256];
        float bj = bm[tid];
        sMch[tid] = sigmoidf_(fmaxf(aA + bj, 0.f) + fmaxf(aM + bj, 0.f));
    }
    __syncthreads();

    // ---------------- node attention ----------------
    // row max over (h * mch) — mch folded, no in-place scale pass
    for (int r = wrp; r < NN; r += 16){
        float mx = -3.0e38f;
#pragma unroll
        for (int t = 0; t < 8; t++){
            int f = lane + 32*t;
            mx = fmaxf(mx, sAT[f*RS + r] * sMch[f]);
        }
#pragma unroll
        for (int o = 16; o; o >>= 1)
            mx = fmaxf(mx, __shfl_down_sync(0xffffffffu, mx, o));
        if (lane == 0) sHmax[r] = mx;
    }
    __syncthreads();
    // 1->1 GCN with symmetric norm + sigmoid
    if (tid < NN){
        float s = 0.f;
        int beg = sOff[tid], end = sOff[tid+1];
        for (int t = beg; t < end; t++){
            int ss = sS[sIdx[t]];
            s += sDinv[ss] * sHmax[ss];
        }
        float aggv = sDinv[tid] * s * wgp[0] + bgp[0];
        sMno[tid] = sigmoidf_(aggv);
    }
    __syncthreads();

    // ---------------- final write (mch * mno folded) ----------------
    {
        float* op = outg + (size_t)g*NN*FD;
        for (int i = tid; i < NN*FD; i += NT){
            int r = i >> 8, f = i & 255;
            op[i] = sAT[f*RS + r] * sMch[f] * sMno[r];
        }
    }
}

extern "C" void kernel_launch(void* const* d_in, const int* in_sizes, int n_in,
                              void* d_out, int out_size)
{
    const float* x   = (const float*)d_in[0];
    const void*  ei  = d_in[1];
    const float* W0  = (const float*)d_in[2];
    const float* as0 = (const float*)d_in[3];
    const float* ad0 = (const float*)d_in[4];
    const float* b0  = (const float*)d_in[5];
    const float* W1  = (const float*)d_in[6];
    const float* as1 = (const float*)d_in[7];
    const float* ad1 = (const float*)d_in[8];
    const float* b1  = (const float*)d_in[9];
    const float* Wm  = (const float*)d_in[10];
    const float* bm  = (const float*)d_in[11];
    const float* wg  = (const float*)d_in[12];
    const float* bg  = (const float*)d_in[13];
    float* out = (float*)d_out;

    int B = in_sizes[0] / (NN*FD);

    cudaFuncSetAttribute(gcab_kernel,
                         cudaFuncAttributeMaxDynamicSharedMemorySize,
                         SMEM_BYTES);
    gcab_kernel<<<B, NT, SMEM_BYTES>>>(x, ei, W0, as0, ad0, b0,
                                       W1, as1, ad1, b1, Wm, bm, wg, bg, out);
}